// round 3
// baseline (speedup 1.0000x reference)
#include <cuda_runtime.h>

#define BATCH 2048
#define TT    512
#define HID   64
#define GATES 256   // 4*HID
#define NB    8     // batch rows per CTA
#define NTHR  128   // each thread owns gate columns tid and tid+128

typedef unsigned long long u64;

__device__ __forceinline__ u64 ffma2(u64 a, u64 b, u64 c) {
    u64 d;
    asm("fma.rn.f32x2 %0, %1, %2, %3;" : "=l"(d) : "l"(a), "l"(b), "l"(c));
    return d;
}

__device__ __forceinline__ u64 pack2(float lo, float hi) {
    u64 r;
    asm("mov.b64 %0, {%1, %2};" : "=l"(r) : "f"(lo), "f"(hi));
    return r;
}

__device__ __forceinline__ float sum2(u64 v) {
    float lo, hi;
    asm("mov.b64 {%0, %1}, %2;" : "=f"(lo), "=f"(hi) : "l"(v));
    return lo + hi;
}

__device__ __forceinline__ float fast_sigmoid(float v) {
    return 1.0f / (1.0f + __expf(-v));
}

__device__ __forceinline__ float fast_tanh(float v) {
    float av = fabsf(v);
    float e  = __expf(-2.0f * av);
    float th = (1.0f - e) / (1.0f + e);
    return copysignf(th, v);
}

__global__ __launch_bounds__(NTHR, 2)
void lstm_kernel(const float* __restrict__ x,
                 const float* __restrict__ W_ih,
                 const float* __restrict__ W_hh,
                 const float* __restrict__ b_ih,
                 const float* __restrict__ b_hh,
                 const float* __restrict__ W_d,
                 const float* __restrict__ b_d,
                 float* __restrict__ out) {
    __shared__ float x_s[NB][TT];      // 16 KB
    __shared__ float h_s[NB][HID];     // 2 KB
    __shared__ float g_s[NB][GATES];   // 8 KB

    const int tid  = threadIdx.x;
    const int colA = tid;              // gate column A: i/f range [0,128)
    const int colB = tid + 128;        // gate column B: g/o range [128,256)
    const int row0 = blockIdx.x * NB;

    // --- W_hh rows for both owned columns, packed f32x2, in registers ---
    u64 wa[HID / 2], wb[HID / 2];
    {
        const ulonglong2* pa = reinterpret_cast<const ulonglong2*>(W_hh + colA * HID);
        const ulonglong2* pb = reinterpret_cast<const ulonglong2*>(W_hh + colB * HID);
#pragma unroll
        for (int q = 0; q < HID / 4; q++) {
            ulonglong2 va = pa[q];
            wa[2 * q + 0] = va.x;  wa[2 * q + 1] = va.y;
            ulonglong2 vb = pb[q];
            wb[2 * q + 0] = vb.x;  wb[2 * q + 1] = vb.y;
        }
    }
    const float wihA  = W_ih[colA];
    const float wihB  = W_ih[colB];
    const float biasA = b_ih[colA] + b_hh[colA];
    const float biasB = b_ih[colB] + b_hh[colB];
    const bool  tanhB = (tid < 64);    // colB in [128,192) -> g gate (warp-uniform)

    // --- stage x slab (coalesced) ---
    for (int i = tid; i < NB * TT; i += NTHR) {
        int r = i >> 9;
        int t = i & (TT - 1);
        x_s[r][t] = x[(row0 + r) * TT + t];
    }
    for (int i = tid; i < NB * HID; i += NTHR)
        ((float*)h_s)[i] = 0.0f;

    // --- phase-2 ownership: 4 (row,unit) pairs per thread ---
    float cc[4] = {0.f, 0.f, 0.f, 0.f};
    int pr[4], pm[4];
#pragma unroll
    for (int p = 0; p < 4; p++) {
        int idx = tid + p * NTHR;      // in [0, 512)
        pr[p] = idx >> 6;
        pm[p] = idx & 63;
    }

    __syncthreads();

    for (int t = 0; t < TT; t++) {
        // ---------- phase 1: gates for two columns, shared h4 loads ----------
        u64 accA[NB], accB[NB];
#pragma unroll
        for (int r = 0; r < NB; r++) {
            float xv = x_s[r][t];
            accA[r] = pack2(fmaf(xv, wihA, biasA), 0.0f);
            accB[r] = pack2(fmaf(xv, wihB, biasB), 0.0f);
        }

#pragma unroll
        for (int k4 = 0; k4 < HID; k4 += 4) {
            const u64 wA0 = wa[(k4 >> 1) + 0], wA1 = wa[(k4 >> 1) + 1];
            const u64 wB0 = wb[(k4 >> 1) + 0], wB1 = wb[(k4 >> 1) + 1];
#pragma unroll
            for (int r = 0; r < NB; r++) {
                ulonglong2 h4 = *reinterpret_cast<const ulonglong2*>(&h_s[r][k4]);
                accA[r] = ffma2(wA0, h4.x, accA[r]);
                accA[r] = ffma2(wA1, h4.y, accA[r]);
                accB[r] = ffma2(wB0, h4.x, accB[r]);
                accB[r] = ffma2(wB1, h4.y, accB[r]);
            }
        }

        // colA: always sigmoid (i or f)
#pragma unroll
        for (int r = 0; r < NB; r++) g_s[r][colA] = fast_sigmoid(sum2(accA[r]));
        // colB: tanh (g) for tid<64, sigmoid (o) otherwise — warp-uniform
        if (tanhB) {
#pragma unroll
            for (int r = 0; r < NB; r++) g_s[r][colB] = fast_tanh(sum2(accB[r]));
        } else {
#pragma unroll
            for (int r = 0; r < NB; r++) g_s[r][colB] = fast_sigmoid(sum2(accB[r]));
        }
        __syncthreads();

        // ---------- phase 2: cell/hidden update (4 pairs per thread) ----------
#pragma unroll
        for (int p = 0; p < 4; p++) {
            int r = pr[p], m = pm[p];
            float i_ = g_s[r][m];
            float f_ = g_s[r][64 + m];
            float gg = g_s[r][128 + m];
            float o_ = g_s[r][192 + m];
            cc[p] = fmaf(f_, cc[p], i_ * gg);
            h_s[r][m] = o_ * fast_tanh(cc[p]);
        }
        __syncthreads();
    }

    // ---------- final projection ----------
    if (tid < NB) {
        float s = b_d[0];
#pragma unroll
        for (int m = 0; m < HID; m++)
            s = fmaf(h_s[tid][m], W_d[m], s);
        out[row0 + tid] = s;
    }
}

extern "C" void kernel_launch(void* const* d_in, const int* in_sizes, int n_in,
                              void* d_out, int out_size) {
    const float* x    = (const float*)d_in[0];
    const float* W_ih = (const float*)d_in[1];
    const float* W_hh = (const float*)d_in[2];
    const float* b_ih = (const float*)d_in[3];
    const float* b_hh = (const float*)d_in[4];
    const float* W_d  = (const float*)d_in[5];
    const float* b_d  = (const float*)d_in[6];
    float* out = (float*)d_out;

    lstm_kernel<<<BATCH / NB, NTHR>>>(x, W_ih, W_hh, b_ih, b_hh, W_d, b_d, out);
}

// round 5
// speedup vs baseline: 1.1831x; 1.1831x over previous
#include <cuda_runtime.h>

#define BATCH 2048
#define TT    512
#define HID   64
#define GATES 256   // 4*HID
#define NB    7     // batch rows per CTA (296 CTAs = exactly 2 per SM)
#define NCTA  296
#define NTHR  256

typedef unsigned long long u64;

__device__ __forceinline__ u64 ffma2(u64 a, u64 b, u64 c) {
    u64 d;
    asm("fma.rn.f32x2 %0, %1, %2, %3;" : "=l"(d) : "l"(a), "l"(b), "l"(c));
    return d;
}

__device__ __forceinline__ u64 pack2(float lo, float hi) {
    u64 r;
    asm("mov.b64 %0, {%1, %2};" : "=l"(r) : "f"(lo), "f"(hi));
    return r;
}

__device__ __forceinline__ float sum2(u64 v) {
    float lo, hi;
    asm("mov.b64 {%0, %1}, %2;" : "=f"(lo), "=f"(hi) : "l"(v));
    return lo + hi;
}

__device__ __forceinline__ float fast_sigmoid(float v) {
    return 1.0f / (1.0f + __expf(-v));
}

__device__ __forceinline__ float fast_tanh(float v) {
    float av = fabsf(v);
    float e  = __expf(-2.0f * av);
    float th = (1.0f - e) / (1.0f + e);
    return copysignf(th, v);
}

__global__ __launch_bounds__(NTHR, 2)
void lstm_kernel(const float* __restrict__ x,
                 const float* __restrict__ W_ih,
                 const float* __restrict__ W_hh,
                 const float* __restrict__ b_ih,
                 const float* __restrict__ b_hh,
                 const float* __restrict__ W_d,
                 const float* __restrict__ b_d,
                 float* __restrict__ out) {
    __shared__ float x_s[NB][TT];      // 14 KB
    __shared__ float h_s[NB][HID];     // 1.75 KB
    __shared__ float g_s[NB][GATES];   // 7 KB

    const int tid  = threadIdx.x;      // gate column j in [0,256)
    const int row0 = blockIdx.x * NB;

    // --- per-thread W_hh row, packed f32x2, in registers ---
    u64 w2[HID / 2];
    {
        const ulonglong2* wp = reinterpret_cast<const ulonglong2*>(W_hh + tid * HID);
#pragma unroll
        for (int q = 0; q < HID / 4; q++) {
            ulonglong2 v = wp[q];      // 16 B = 4 floats = 2 packed pairs
            w2[2 * q + 0] = v.x;
            w2[2 * q + 1] = v.y;
        }
    }
    const float wih  = W_ih[tid];
    const float bias = b_ih[tid] + b_hh[tid];
    const int gtype  = tid >> 6;       // 0:i 1:f 2:g 3:o (warp-uniform)

    // --- stage x slab (coalesced, clamp rows past BATCH) ---
    for (int i = tid; i < NB * TT; i += NTHR) {
        int r = i / TT;
        int t = i % TT;
        int gr = row0 + r;
        if (gr > BATCH - 1) gr = BATCH - 1;
        x_s[r][t] = x[gr * TT + t];
    }
    for (int i = tid; i < NB * HID; i += NTHR)
        ((float*)h_s)[i] = 0.0f;

    // --- phase-2 ownership: NB*HID = 448 states; thread owns tid, and tid+256 if <448 ---
    float c0 = 0.0f, c1 = 0.0f;
    const int r0a = tid >> 6,          m0 = tid & 63;
    const bool has1 = (tid < NB * HID - NTHR);          // tid < 192
    const int idx1 = tid + NTHR;
    const int r1a = idx1 >> 6,         m1 = idx1 & 63;

    __syncthreads();

    for (int t = 0; t < TT; t++) {
        // ---------- phase 1: gate pre-activations ----------
        u64 acc[NB];
#pragma unroll
        for (int r = 0; r < NB; r++)
            acc[r] = pack2(fmaf(x_s[r][t], wih, bias), 0.0f);

#pragma unroll
        for (int r = 0; r < NB; r++) {
            // half-row batches: 8 back-to-back LDS.128 (MLP=8), then 16 FFMA2
#pragma unroll
            for (int half = 0; half < 2; half++) {
                ulonglong2 hv[8];
#pragma unroll
                for (int q = 0; q < 8; q++)     // covers floats [half*32 + q*4 .. +3]
                    hv[q] = *reinterpret_cast<const ulonglong2*>(&h_s[r][half * 32 + q * 4]);
#pragma unroll
                for (int q = 0; q < 8; q++) {
                    int base = half * 16 + 2 * q;   // w2 pair index
                    acc[r] = ffma2(w2[base + 0], hv[q].x, acc[r]);
                    acc[r] = ffma2(w2[base + 1], hv[q].y, acc[r]);
                }
            }
        }

        if (gtype == 2) {   // g gate: tanh (warp-uniform)
#pragma unroll
            for (int r = 0; r < NB; r++) g_s[r][tid] = fast_tanh(sum2(acc[r]));
        } else {            // i, f, o: sigmoid
#pragma unroll
            for (int r = 0; r < NB; r++) g_s[r][tid] = fast_sigmoid(sum2(acc[r]));
        }
        __syncthreads();

        // ---------- phase 2: cell/hidden update ----------
        {
            float i_ = g_s[r0a][m0];
            float f_ = g_s[r0a][64 + m0];
            float gg = g_s[r0a][128 + m0];
            float o_ = g_s[r0a][192 + m0];
            c0 = fmaf(f_, c0, i_ * gg);
            h_s[r0a][m0] = o_ * fast_tanh(c0);
        }
        if (has1) {
            float i_ = g_s[r1a][m1];
            float f_ = g_s[r1a][64 + m1];
            float gg = g_s[r1a][128 + m1];
            float o_ = g_s[r1a][192 + m1];
            c1 = fmaf(f_, c1, i_ * gg);
            h_s[r1a][m1] = o_ * fast_tanh(c1);
        }
        __syncthreads();
    }

    // ---------- final projection ----------
    if (tid < NB && row0 + tid < BATCH) {
        float s = b_d[0];
#pragma unroll
        for (int m = 0; m < HID; m++)
            s = fmaf(h_s[tid][m], W_d[m], s);
        out[row0 + tid] = s;
    }
}

extern "C" void kernel_launch(void* const* d_in, const int* in_sizes, int n_in,
                              void* d_out, int out_size) {
    const float* x    = (const float*)d_in[0];
    const float* W_ih = (const float*)d_in[1];
    const float* W_hh = (const float*)d_in[2];
    const float* b_ih = (const float*)d_in[3];
    const float* b_hh = (const float*)d_in[4];
    const float* W_d  = (const float*)d_in[5];
    const float* b_d  = (const float*)d_in[6];
    float* out = (float*)d_out;

    lstm_kernel<<<NCTA, NTHR>>>(x, W_ih, W_hh, b_ih, b_hh, W_d, b_d, out);
}